// round 1
// baseline (speedup 1.0000x reference)
#include <cuda_runtime.h>
#include <cuda_bf16.h>

// DiscriminativeLoss: two-pass segment reduction + hinge losses.
//   data  : [D=32][N=524288] float32 (dim-major, points contiguous)
//   labels: [N] int32 in [0,16)
//   out   : scalar float32
//
// K1 (segment sums): per 128-point tile, counting-sort point indices by label
// into 16 shared lists (1 shared atomic per point), then thread (k, dr) walks
// list k accumulating dims dr and dr+16 in registers. Avoids the 16x dense
// one-hot GEMM and the 32x atomic scatter.
// K2: centers + pairwise-distance hinge + reg term (single block).
// K3: var term, centers staged in shared with [d][k] layout (bank-conflict-free).

#define DD 32
#define KK 16
#define TILE 128
#define XSTR 131   // padded row stride (floats) for s_x[d][n]; gcd(3,32)=1 spreads banks

__device__ float g_sums[KK * DD];     // [k][d]
__device__ float g_counts[KK];
__device__ float g_centers[DD * KK];  // [d][k] for K3's lookup layout

__global__ void k_zero() {
    int t = blockIdx.x * blockDim.x + threadIdx.x;
    if (t < KK * DD) g_sums[t] = 0.f;
    if (t < KK) g_counts[t] = 0.f;
}

__global__ __launch_bounds__(256)
void k_sums(const float* __restrict__ data, const int* __restrict__ labels, int npts) {
    __shared__ float s_x[DD * XSTR];          // ~16.4 KB
    __shared__ unsigned char s_list[KK][TILE]; // 2 KB
    __shared__ int s_cnt[KK];

    const int t  = threadIdx.x;
    const int k  = t >> 4;   // cluster this thread owns
    const int dr = t & 15;   // dims dr and dr+16

    float acc0 = 0.f, acc1 = 0.f;
    int ccnt = 0;

    const int ntiles = npts / TILE;
    for (int tile = blockIdx.x; tile < ntiles; tile += gridDim.x) {
        const int n0 = tile * TILE;
        __syncthreads();                       // prev phase-B readers done
        if (t < KK) s_cnt[t] = 0;

        // Load tile: 1024 float4 loads, fully coalesced (points contiguous per dim)
        #pragma unroll
        for (int j = 0; j < 4; j++) {
            int idx = t + j * 256;             // 0..1023
            int d  = idx >> 5;                 // 32 float4 per dim row
            int n4 = idx & 31;
            float4 v = *reinterpret_cast<const float4*>(
                data + (size_t)d * npts + n0 + (n4 << 2));
            float* p = s_x + d * XSTR + (n4 << 2);
            p[0] = v.x; p[1] = v.y; p[2] = v.z; p[3] = v.w;
        }
        __syncthreads();                       // s_cnt zeroed, s_x filled

        // Phase A: compact point indices into per-label lists (1 atomic/point)
        if (t < TILE) {
            int lab = labels[n0 + t];
            int pos = atomicAdd(&s_cnt[lab], 1);
            s_list[lab][pos] = (unsigned char)t;
        }
        __syncthreads();                       // lists ready

        // Phase B: thread (k, dr) sums its own cluster's points, 2 dims each
        const int cnt = s_cnt[k];
        const float* r0 = s_x + dr * XSTR;
        const float* r1 = s_x + (dr + 16) * XSTR;
        const unsigned char* lst = s_list[k];
        for (int i = 0; i < cnt; i++) {
            int idx = lst[i];
            acc0 += r0[idx];
            acc1 += r1[idx];
        }
        if (dr == 0) ccnt += cnt;
    }
    atomicAdd(&g_sums[k * DD + dr], acc0);
    atomicAdd(&g_sums[k * DD + dr + 16], acc1);
    if (dr == 0) atomicAdd(&g_counts[k], (float)ccnt);
}

__global__ __launch_bounds__(256)
void k_centers(float* __restrict__ out) {
    __shared__ float s_c[KK * DD];  // [k][d]
    __shared__ float s_red[8];
    __shared__ float s_reg[KK];
    const int t = threadIdx.x;

    for (int j = t; j < KK * DD; j += 256) {
        int kk = j >> 5, dd = j & 31;
        float c = g_sums[j] / g_counts[kk];
        s_c[j] = c;
        g_centers[dd * KK + kk] = c;           // transpose for K3
    }
    __syncthreads();

    // reg term: one thread per cluster norm
    if (t < KK) {
        float s = 0.f;
        #pragma unroll
        for (int dd = 0; dd < DD; dd++) { float c = s_c[t * DD + dd]; s += c * c; }
        s_reg[t] = sqrtf(s);
    }

    // distance term: thread = ordered pair (i, j)
    const int i = t >> 4, j = t & 15;
    float dsum = 0.f;
    if (i != j) {
        float sq = 0.f;
        #pragma unroll
        for (int dd = 0; dd < DD; dd++) {
            float df = s_c[i * DD + dd] - s_c[j * DD + dd];
            sq += df * df;
        }
        float h = fmaxf(3.0f - sqrtf(sq), 0.f);   // 2*DELTA_DIST = 3.0
        dsum = h * h;
    }
    #pragma unroll
    for (int off = 16; off > 0; off >>= 1)
        dsum += __shfl_down_sync(0xffffffffu, dsum, off);
    if ((t & 31) == 0) s_red[t >> 5] = dsum;
    __syncthreads();
    if (t == 0) {
        float tot = 0.f;
        #pragma unroll
        for (int w = 0; w < 8; w++) tot += s_red[w];
        float reg = 0.f;
        #pragma unroll
        for (int kk = 0; kk < KK; kk++) reg += s_reg[kk];
        out[0] = tot / (float)(KK * (KK - 1)) + 0.001f * reg / (float)KK;
    }
}

__global__ __launch_bounds__(256)
void k_var(const float* __restrict__ data, const int* __restrict__ labels,
           int npts, float* __restrict__ out) {
    __shared__ float s_c[DD * KK];   // [d][k]: 16 banks map 1:1 -> conflict-free
    __shared__ float s_red[8];
    for (int j = threadIdx.x; j < DD * KK; j += 256) s_c[j] = g_centers[j];
    __syncthreads();

    float vsum = 0.f;
    const int nq = npts >> 2;
    const int stride = gridDim.x * blockDim.x;
    for (int q = blockIdx.x * blockDim.x + threadIdx.x; q < nq; q += stride) {
        const int n = q << 2;
        const int4 lab = *reinterpret_cast<const int4*>(labels + n);
        float a0 = 0.f, a1 = 0.f, a2 = 0.f, a3 = 0.f;
        #pragma unroll 8
        for (int d = 0; d < DD; d++) {
            const float4 v = *reinterpret_cast<const float4*>(
                data + (size_t)d * npts + n);
            const float* cr = s_c + d * KK;
            float d0 = cr[lab.x] - v.x; a0 = fmaf(d0, d0, a0);
            float d1 = cr[lab.y] - v.y; a1 = fmaf(d1, d1, a1);
            float d2 = cr[lab.z] - v.z; a2 = fmaf(d2, d2, a2);
            float d3 = cr[lab.w] - v.w; a3 = fmaf(d3, d3, a3);
        }
        float h0 = fmaxf(sqrtf(a0) - 0.5f, 0.f);
        float h1 = fmaxf(sqrtf(a1) - 0.5f, 0.f);
        float h2 = fmaxf(sqrtf(a2) - 0.5f, 0.f);
        float h3 = fmaxf(sqrtf(a3) - 0.5f, 0.f);
        vsum += h0 * h0 + h1 * h1 + h2 * h2 + h3 * h3;
    }
    #pragma unroll
    for (int off = 16; off > 0; off >>= 1)
        vsum += __shfl_down_sync(0xffffffffu, vsum, off);
    if ((threadIdx.x & 31) == 0) s_red[threadIdx.x >> 5] = vsum;
    __syncthreads();
    if (threadIdx.x == 0) {
        float tot = 0.f;
        #pragma unroll
        for (int w = 0; w < 8; w++) tot += s_red[w];
        atomicAdd(out, tot * (1.0f / KK));   // VAR_WEIGHT / K
    }
}

extern "C" void kernel_launch(void* const* d_in, const int* in_sizes, int n_in,
                              void* d_out, int out_size) {
    const float* data   = (const float*)d_in[0];
    const int*   labels = (const int*)d_in[1];
    const int    npts   = in_sizes[1];       // 512*1024
    float* out = (float*)d_out;

    k_zero<<<3, 256>>>();
    k_sums<<<592, 256>>>(data, labels, npts);     // 4 blocks/SM, grid-stride tiles
    k_centers<<<1, 256>>>(out);                   // also writes dist+reg into out
    k_var<<<592, 256>>>(data, labels, npts, out); // atomicAdd var term
}

// round 2
// speedup vs baseline: 1.0643x; 1.0643x over previous
#include <cuda_runtime.h>
#include <cuda_bf16.h>

// DiscriminativeLoss, 2-launch version.
//   data  : [D=32][N=524288] float32 (dim-major), labels: [N] int32 in [0,16)
//
// K1 (k_sums): per 256-point tile, counting-sort point indices by label into
// 16 shared lists (1 shared atomic per point); thread (k, dr) walks list k
// accumulating dims dr, dr+16. atomicAdd partials into g_sums/g_counts.
// K2 (k_var): every block computes centers from g_sums in smem ([d][k] layout,
// bank-conflict-free lookups), accumulates the var hinge over 2 points/thread
// (fine granularity -> ~85% occupancy for latency hiding), atomicAdds into
// g_var. The LAST block to finish adds the dist + reg terms, writes out[0],
// and re-zeroes all accumulators (graph-replay invariant; statics start at 0).

#define DD 32
#define KK 16
#define TILE 256
#define XSTR 259   // padded row stride; odd -> phase-B rows spread across banks

__device__ float g_sums[KK * DD];   // [k][d]
__device__ float g_counts[KK];
__device__ float g_var;
__device__ unsigned int g_done;

__global__ __launch_bounds__(256)
void k_sums(const float* __restrict__ data, const int* __restrict__ labels, int npts) {
    __shared__ float s_x[DD * XSTR];            // ~33.2 KB
    __shared__ unsigned char s_list[KK][TILE];  // 4 KB
    __shared__ int s_cnt[KK];

    const int t  = threadIdx.x;
    const int k  = t >> 4;    // cluster this thread owns
    const int dr = t & 15;    // dims dr and dr+16

    float acc0 = 0.f, acc1 = 0.f;
    int ccnt = 0;

    const int ntiles = npts / TILE;             // 2048
    for (int tile = blockIdx.x; tile < ntiles; tile += gridDim.x) {
        const int n0 = tile * TILE;
        __syncthreads();                        // prev phase-B readers done
        if (t < KK) s_cnt[t] = 0;

        // Load tile: 2048 float4 loads, fully coalesced, 8 in flight/thread
        #pragma unroll
        for (int j = 0; j < 8; j++) {
            int idx = t + j * 256;              // 0..2047
            int d  = idx >> 6;                  // 64 float4 per dim row
            int n4 = idx & 63;
            float4 v = *reinterpret_cast<const float4*>(
                data + (size_t)d * npts + n0 + (n4 << 2));
            float* p = s_x + d * XSTR + (n4 << 2);
            p[0] = v.x; p[1] = v.y; p[2] = v.z; p[3] = v.w;
        }
        // Phase A: compact point indices into per-label lists (1 atomic/point)
        int lab = labels[n0 + t];
        __syncthreads();                        // s_cnt zeroed, s_x filled
        int pos = atomicAdd(&s_cnt[lab], 1);
        s_list[lab][pos] = (unsigned char)t;
        __syncthreads();                        // lists ready

        // Phase B: thread (k, dr) sums its own cluster's points, 2 dims each
        const int cnt = s_cnt[k];
        const float* r0 = s_x + dr * XSTR;
        const float* r1 = s_x + (dr + 16) * XSTR;
        const unsigned char* lst = s_list[k];
        for (int i = 0; i < cnt; i++) {
            int idx = lst[i];
            acc0 += r0[idx];
            acc1 += r1[idx];
        }
        if (dr == 0) ccnt += cnt;
    }
    atomicAdd(&g_sums[k * DD + dr], acc0);
    atomicAdd(&g_sums[k * DD + dr + 16], acc1);
    if (dr == 0) atomicAdd(&g_counts[k], (float)ccnt);
}

__global__ __launch_bounds__(256, 6)
void k_var(const float* __restrict__ data, const int* __restrict__ labels,
           int npts, float* __restrict__ out) {
    __shared__ float s_c[DD * KK];   // [d][k]: 16-entry rows map 1:1 to banks
    __shared__ float s_red[8];
    __shared__ float s_reg[KK];
    __shared__ unsigned int s_rank;
    const int t = threadIdx.x;

    // Every block derives centers (512 divides, trivial; deterministic per block)
    #pragma unroll
    for (int j = t; j < DD * KK; j += 256) {
        int d = j >> 4, kk = j & 15;
        s_c[j] = g_sums[kk * DD + d] / g_counts[kk];
    }
    __syncthreads();

    // Var term: 2 points per thread -> 8192 warps chip-wide for latency hiding
    const int base = (blockIdx.x * 256 + t) * 2;
    float vsum = 0.f;
    if (base < npts) {
        const int2 lab = *reinterpret_cast<const int2*>(labels + base);
        float a0 = 0.f, a1 = 0.f;
        #pragma unroll 8
        for (int d = 0; d < DD; d++) {
            const float2 v = *reinterpret_cast<const float2*>(
                data + (size_t)d * npts + base);
            const float* cr = s_c + d * KK;
            float d0 = cr[lab.x] - v.x; a0 = fmaf(d0, d0, a0);
            float d1 = cr[lab.y] - v.y; a1 = fmaf(d1, d1, a1);
        }
        float h0 = fmaxf(sqrtf(a0) - 0.5f, 0.f);
        float h1 = fmaxf(sqrtf(a1) - 0.5f, 0.f);
        vsum = h0 * h0 + h1 * h1;
    }
    #pragma unroll
    for (int off = 16; off > 0; off >>= 1)
        vsum += __shfl_down_sync(0xffffffffu, vsum, off);
    if ((t & 31) == 0) s_red[t >> 5] = vsum;
    __syncthreads();
    if (t == 0) {
        float tot = 0.f;
        #pragma unroll
        for (int w = 0; w < 8; w++) tot += s_red[w];
        atomicAdd(&g_var, tot);
        __threadfence();
        s_rank = atomicAdd(&g_done, 1u);
    }
    __syncthreads();

    // Last block to finish: dist + reg terms, final write, re-zero for replay
    if (s_rank == gridDim.x - 1) {
        __threadfence();
        __syncthreads();                 // make s_red reusable
        // reg term: one thread per cluster norm
        if (t < KK) {
            float s = 0.f;
            #pragma unroll
            for (int d = 0; d < DD; d++) { float c = s_c[d * KK + t]; s += c * c; }
            s_reg[t] = sqrtf(s);
        }
        // distance term: thread = ordered pair (i, j)
        const int i = t >> 4, j = t & 15;
        float dsum = 0.f;
        if (i != j) {
            float sq = 0.f;
            #pragma unroll
            for (int d = 0; d < DD; d++) {
                float df = s_c[d * KK + i] - s_c[d * KK + j];
                sq += df * df;
            }
            float h = fmaxf(3.0f - sqrtf(sq), 0.f);   // 2*DELTA_DIST
            dsum = h * h;
        }
        #pragma unroll
        for (int off = 16; off > 0; off >>= 1)
            dsum += __shfl_down_sync(0xffffffffu, dsum, off);
        if ((t & 31) == 0) s_red[t >> 5] = dsum;
        __syncthreads();
        if (t == 0) {
            float dtot = 0.f;
            #pragma unroll
            for (int w = 0; w < 8; w++) dtot += s_red[w];
            float reg = 0.f;
            #pragma unroll
            for (int kk = 0; kk < KK; kk++) reg += s_reg[kk];
            float var_total = g_var;     // all adds visible (done-counter + fences)
            out[0] = var_total * (1.0f / KK)
                   + dtot * (1.0f / (KK * (KK - 1)))
                   + 0.001f * reg * (1.0f / KK);
            g_var = 0.f;
            g_done = 0u;
        }
        // re-zero segment accumulators for the next graph replay
        for (int jz = t; jz < KK * DD; jz += 256) g_sums[jz] = 0.f;
        if (t < KK) g_counts[t] = 0.f;
    }
}

extern "C" void kernel_launch(void* const* d_in, const int* in_sizes, int n_in,
                              void* d_out, int out_size) {
    const float* data   = (const float*)d_in[0];
    const int*   labels = (const int*)d_in[1];
    const int    npts   = in_sizes[1];          // 512*1024
    float* out = (float*)d_out;

    k_sums<<<888, 256>>>(data, labels, npts);   // 6 blocks/SM (smem-limited)
    const int vblocks = (npts / 2 + 255) / 256; // 1024
    k_var<<<vblocks, 256>>>(data, labels, npts, out);
}